// round 13
// baseline (speedup 1.0000x reference)
#include <cuda_runtime.h>
#include <cstdint>

// Problem constants
#define C_IN      128
#define H_IN      112
#define W_IN      112
#define N_BATCH   8
#define HO_OUT    56
#define WO_OUT    56

// Tiling (896 tiles, 256 threads, 2 CTAs/SM)
#define TILE_WO    28
#define NTHREADS   256
#define ROW_STRIDE 60                        // floats per staged row (mult of 4)
// CH_STRIDE = exact per-channel footprint (3*60 = 180, mult of 4).
// 180 mod 32 = 20, gcd(20,32)=4 -> channel bases cycle all 8 four-float bank
// residues: a free swizzle, no padding, no overlap.
#define CH_STRIDE  180
#define CBASE(c)   ((c) * CH_STRIDE)

#define XBUF_FLOATS (C_IN * CH_STRIDE)       // 23040 (mult of 8 -> sred u64-aligned)
#define NPART       16
#define RED_FLOATS  (NPART * 9 * TILE_WO)    // 4032
#define SIG_FLOATS  (9 * TILE_WO)            // 252
#define SMEM_BYTES  ((XBUF_FLOATS + RED_FLOATS + SIG_FLOATS) * 4)   // 109,296 B

// Repacked weights: [c][i*3+j][12] (k contiguous, padded 9->12 for LDG.128)
__device__ __align__(16) float g_wpk[C_IN * 9 * 12];
__device__ float g_scale[9];
__device__ float g_shift[9];

__global__ void repack_kernel(const float* __restrict__ cw,
                              const float* __restrict__ bnw,
                              const float* __restrict__ bnb,
                              const float* __restrict__ bnm,
                              const float* __restrict__ bnv)
{
    int idx = blockIdx.x * blockDim.x + threadIdx.x;
    if (idx < C_IN * 81) {
        int c  = idx / 81;
        int r  = idx - c * 81;
        int k  = r / 9;
        int ij = r - k * 9;
        g_wpk[(c * 9 + ij) * 12 + k] = cw[(k * C_IN + c) * 9 + ij];
    }
    if (idx < 9) {
        float sc = bnw[idx] * rsqrtf(bnv[idx] + 1e-5f);
        g_scale[idx] = sc;
        g_shift[idx] = bnb[idx] - bnm[idx] * sc;
    }
}

// ---- f32x2 helpers (sm_103a packed fp32) ------------------------------------
__device__ __forceinline__ unsigned long long pk2(float v) {
    unsigned long long r;
    asm("mov.b64 %0, {%1, %1};" : "=l"(r) : "f"(v));
    return r;
}
__device__ __forceinline__ void ffma2(unsigned long long& d,
                                      unsigned long long a, unsigned long long b) {
    asm("fma.rn.f32x2 %0, %1, %2, %0;" : "+l"(d) : "l"(a), "l"(b));
}
__device__ __forceinline__ unsigned long long add2(unsigned long long a,
                                                   unsigned long long b) {
    unsigned long long r;
    asm("add.rn.f32x2 %0, %1, %2;" : "=l"(r) : "l"(a), "l"(b));
    return r;
}
__device__ __forceinline__ void unpk(unsigned long long v, float& lo, float& hi) {
    asm("mov.b64 {%0, %1}, %2;" : "=f"(lo), "=f"(hi) : "l"(v));
}
__device__ __forceinline__ void cp_async4(unsigned saddr, const float* gaddr) {
    asm volatile("cp.async.ca.shared.global [%0], [%1], 4;\n"
                 :: "r"(saddr), "l"(gaddr));
}
__device__ __forceinline__ void cp_async16(unsigned saddr, const float* gaddr) {
    asm volatile("cp.async.cg.shared.global [%0], [%1], 16;\n"
                 :: "r"(saddr), "l"(gaddr));
}

__global__ __launch_bounds__(NTHREADS, 2)
void pasa_fused_kernel(const float* __restrict__ x, float* __restrict__ out)
{
    extern __shared__ float sm[];
    float* sx   = sm;                        // x tile, CH_STRIDE-cycled banks
    float* sred = sm + XBUF_FLOATS;          // [16 part][9 k][28 wo]
    float* ssig = sred + RED_FLOATS;         // [9 k][28 wo]

    const int b   = blockIdx.x;              // 0..895
    const int wt  = b & 1;
    const int ho  = (b >> 1) % HO_OUT;
    const int n   = b / (2 * HO_OUT);
    const int wo0 = wt * TILE_WO;
    const int t   = threadIdx.x;
    const int lane = t & 31;
    const int warp = t >> 5;

    const float* xn = x + (size_t)n * C_IN * H_IN * W_IN;

    // ---------------- Stage x tile: 16B cp.async, 57-col window ------------------
    // Window w=0..56 lives at slot CBASE(c)+60r+3+w. w=0 is the left halo
    // (reflected), w=1..56 is one contiguous 16B-aligned gmem block (cols GB..GB+55).
    // No right halo (max window index is 56 -> never read).
    {
        const int h0 = 2 * ho - 1;
        const int GB = wt ? 56 : 0;          // aligned block start col
        const int HL = wt ? 55 : 1;          // left-halo source col (reflected)
        const int i  = lane & 15;            // 0..13 chunk, 14 halo, 15 idle
        const unsigned xb_sa = (unsigned)__cvta_generic_to_shared(sx);
#pragma unroll 4
        for (int j = 0; j < 24; j++) {
            const int rowidx = (warp * 24 + j) * 2 + (lane >> 4);   // 0..383
            const int c = rowidx / 3;
            const int r = rowidx - 3 * c;
            int rr = h0 + r;  if (rr < 0) rr = -rr;                 // top edge only
            const float* grow = xn + (size_t)c * (H_IN * W_IN) + rr * W_IN;
            const unsigned sa = xb_sa + (unsigned)((CBASE(c) + ROW_STRIDE * r) * 4);
            if (i < 14)       cp_async16(sa + 16 + (i << 4), grow + GB + 4 * i);
            else if (i == 14) cp_async4(sa + 12, grow + HL);
        }
    }
    asm volatile("cp.async.commit_group;\n" ::: "memory");
    asm volatile("cp.async.wait_group 0;\n" ::: "memory");
    __syncthreads();

    // ---------------- Sigma conv: FFMA2, k packed in pairs ----------------------
    // thread = (wg = t&3 : 4 groups of 7 wo) x (cg = t>>2 : 64 groups of 2 ch)
    const int wg = t & 3;
    const int cg = t >> 2;

    unsigned long long A0[7], A1[7], A2[7], A3[7];   // k pairs (0,1)(2,3)(4,5)(6,7)
    float A8[7];
#pragma unroll
    for (int u = 0; u < 7; u++) { A0[u]=0ull; A1[u]=0ull; A2[u]=0ull; A3[u]=0ull; A8[u]=0.0f; }

#pragma unroll
    for (int cc2 = 0; cc2 < 2; cc2++) {
        const int c = cg * 2 + cc2;
        const float* wrow = g_wpk + c * 108;
        const float* xc   = sx + CBASE(c) + 3 + wg * 14;
#pragma unroll
        for (int i = 0; i < 3; i++) {
            // xr[0] is at an odd float index; xr[1..14] start even -> 7x LDS.64
            float xr[15];
            xr[0] = xc[i * ROW_STRIDE];
            const float2* xp = reinterpret_cast<const float2*>(xc + i * ROW_STRIDE + 1);
#pragma unroll
            for (int s = 0; s < 7; s++) {
                const float2 v = xp[s];
                xr[1 + 2 * s] = v.x;
                xr[2 + 2 * s] = v.y;
            }
#pragma unroll
            for (int j = 0; j < 3; j++) {
                const int off = (i * 3 + j) * 12;
                const ulonglong2 pA = *reinterpret_cast<const ulonglong2*>(wrow + off);
                const ulonglong2 pB = *reinterpret_cast<const ulonglong2*>(wrow + off + 4);
                const float      w8 = wrow[off + 8];
#pragma unroll
                for (int u = 0; u < 7; u++) {
                    const float xv = xr[2 * u + j];
                    const unsigned long long x2 = pk2(xv);
                    ffma2(A0[u], x2, pA.x);
                    ffma2(A1[u], x2, pA.y);
                    ffma2(A2[u], x2, pB.x);
                    ffma2(A3[u], x2, pB.y);
                    A8[u] = fmaf(xv, w8, A8[u]);
                }
            }
        }
    }

    // ---------------- 2-level butterfly (lane bits 2,3) -------------------------
#pragma unroll
    for (int u = 0; u < 7; u++) {
        unsigned long long v;
        v = A0[u]; v = add2(v, __shfl_xor_sync(0xffffffffu, v, 4)); v = add2(v, __shfl_xor_sync(0xffffffffu, v, 8)); A0[u] = v;
        v = A1[u]; v = add2(v, __shfl_xor_sync(0xffffffffu, v, 4)); v = add2(v, __shfl_xor_sync(0xffffffffu, v, 8)); A1[u] = v;
        v = A2[u]; v = add2(v, __shfl_xor_sync(0xffffffffu, v, 4)); v = add2(v, __shfl_xor_sync(0xffffffffu, v, 8)); A2[u] = v;
        v = A3[u]; v = add2(v, __shfl_xor_sync(0xffffffffu, v, 4)); v = add2(v, __shfl_xor_sync(0xffffffffu, v, 8)); A3[u] = v;
        float f = A8[u];
        f += __shfl_xor_sync(0xffffffffu, f, 4);
        f += __shfl_xor_sync(0xffffffffu, f, 8);
        A8[u] = f;
    }

    // Lanes {0..3, 16..19} of each warp hold sums over 4 cg (= 8 channels)
    if ((lane & 12) == 0) {
        const int p = (warp << 1) | (lane >> 4);     // 16 partials
        float* rp = sred + p * 252 + wg * 7;         // p*252 + k*28 + wg*7+u
        float lo, hi;
#pragma unroll
        for (int u = 0; u < 7; u++) {
            unpk(A0[u], lo, hi); rp[0*28+u] = lo; rp[1*28+u] = hi;
            unpk(A1[u], lo, hi); rp[2*28+u] = lo; rp[3*28+u] = hi;
            unpk(A2[u], lo, hi); rp[4*28+u] = lo; rp[5*28+u] = hi;
            unpk(A3[u], lo, hi); rp[6*28+u] = lo; rp[7*28+u] = hi;
            rp[8*28+u] = A8[u];
        }
    }
    __syncthreads();

    // ---------------- 16-way reduce (packed) + frozen-BN + clamp -----------------
    if (t < 126) {                           // 2 consecutive entries per thread
        const unsigned long long* r64 = reinterpret_cast<const unsigned long long*>(sred);
        unsigned long long s2 = r64[t];
#pragma unroll
        for (int p = 1; p < NPART; p++) s2 = add2(s2, r64[p * 126 + t]);
        const int k = t / 14;                // pairs never straddle k
        const float sc = g_scale[k], sh = g_shift[k];
        float lo, hi; unpk(s2, lo, hi);
        lo = fmaxf(fmaf(lo, sc, sh), 1e-4f);
        hi = fmaxf(fmaf(hi, sc, sh), 1e-4f);
        ssig[2 * t]     = lo;
        ssig[2 * t + 1] = hi;
    }
    __syncthreads();

    // ---------------- Normalize over the 9 taps ----------------------------------
    if (t < TILE_WO) {
        float sum = 0.0f;
#pragma unroll
        for (int k = 0; k < 9; k++) sum += ssig[k * TILE_WO + t];
        const float inv = 1.0f / sum;
#pragma unroll
        for (int k = 0; k < 9; k++) ssig[k * TILE_WO + t] *= inv;
    }
    __syncthreads();

    // ---------------- Apply: 224 threads, wol-PAIRS, LDS.64 + STG.64 -------------
    // thread = (cl 0..15, m 0..13) -> outputs (2m, 2m+1) for channels c = cl+16*it.
    // Shared 5-value window per row: base[0] scalar (odd slot), then 2x float2.
    if (t < 16 * 14) {
        const int cl = t / 14;               // 0..15
        const int m  = t - cl * 14;          // 0..13  (wol pair = 2m, 2m+1)

        float s0[9], s1[9];
#pragma unroll
        for (int k = 0; k < 9; k++) {
            const float2 sv = *reinterpret_cast<const float2*>(ssig + k * TILE_WO + 2 * m);
            s0[k] = sv.x;  s1[k] = sv.y;
        }

        float* ob = out + ((size_t)n * C_IN + cl) * (HO_OUT * WO_OUT)
                        + (size_t)ho * WO_OUT + wo0 + 2 * m;
#pragma unroll 2
        for (int it = 0; it < 8; it++) {
            const int c = cl + 16 * it;
            const float* base = sx + CBASE(c) + 3 + 4 * m;
            float o0 = 0.0f, o1 = 0.0f;
#pragma unroll
            for (int i = 0; i < 3; i++) {
                const float  v0 = base[i * ROW_STRIDE];
                const float2 a  = *reinterpret_cast<const float2*>(base + i * ROW_STRIDE + 1);
                const float2 bb = *reinterpret_cast<const float2*>(base + i * ROW_STRIDE + 3);
                o0 = fmaf(v0,   s0[3*i+0], o0);
                o0 = fmaf(a.x,  s0[3*i+1], o0);
                o0 = fmaf(a.y,  s0[3*i+2], o0);
                o1 = fmaf(a.y,  s1[3*i+0], o1);
                o1 = fmaf(bb.x, s1[3*i+1], o1);
                o1 = fmaf(bb.y, s1[3*i+2], o1);
            }
            *reinterpret_cast<float2*>(ob + (size_t)(16 * it) * (HO_OUT * WO_OUT))
                = make_float2(o0, o1);
        }
    }
}

extern "C" void kernel_launch(void* const* d_in, const int* in_sizes, int n_in,
                              void* d_out, int out_size)
{
    const float* x   = (const float*)d_in[0];
    const float* cw  = (const float*)d_in[1];
    const float* bnw = (const float*)d_in[2];
    const float* bnb = (const float*)d_in[3];
    const float* bnm = (const float*)d_in[4];
    const float* bnv = (const float*)d_in[5];
    float* out = (float*)d_out;

    repack_kernel<<<(C_IN * 81 + 255) / 256, 256>>>(cw, bnw, bnb, bnm, bnv);

    cudaFuncSetAttribute(pasa_fused_kernel,
                         cudaFuncAttributeMaxDynamicSharedMemorySize, SMEM_BYTES);
    const int grid = N_BATCH * HO_OUT * 2;   // 896 blocks
    pasa_fused_kernel<<<grid, NTHREADS, SMEM_BYTES>>>(x, out);
}